// round 10
// baseline (speedup 1.0000x reference)
#include <cuda_runtime.h>

#define NN 50000
#define EE 800000
#define HD 64
#define ED 8
#define LN_EPS 1e-5f
#define ETILES (EE / 64)            // 12500
#define NTILES ((NN + 31) / 32)     // 1563

// Padded row strides (floats): 132*4B = 528B, 16B-aligned, rows shift 4 banks.
#define HSTRIDE 132     // 128-wide rows
#define WTSTRIDE 132    // transposed weight rows ([col][k])
#define RSTRIDE 68      // 64-wide rows

// Scratch (static device arrays: allocation-free rule)
__device__ float d_X[NN * 256];     // [Xs(128) | Xd(128)] per node = h@W1s | h@W1d
__device__ float d_agg[NN * HD];    // scatter-add destination
__device__ int   d_src[EE];         // edge sources (int32, post-conversion)
__device__ int   d_dst[EE];         // edge destinations
__device__ int   d_is64;            // 1 if edge_index buffer is int64

// ---- packed f32x2 helpers (Blackwell FFMA2; only reachable via PTX) ----
#define FMA2(acc, a, b) \
    asm("fma.rn.f32x2 %0, %1, %2, %0;" : "+l"(acc) : "l"(a), "l"(b))
#define ADD2(d, a, b) \
    asm("add.rn.f32x2 %0, %1, %2;" : "=l"(d) : "l"(a), "l"(b))
#define PACK2(d, s) \
    asm("mov.b64 %0, {%1, %1};" : "=l"(d) : "f"(s))

__device__ __forceinline__ float hadd_f32x2(unsigned long long v) {
    float lo, hi;
    asm("mov.b64 {%0, %1}, %2;" : "=f"(lo), "=f"(hi) : "l"(v));
    return lo + hi;
}

__device__ __forceinline__ void unpack2(unsigned long long v, float& lo, float& hi) {
    asm("mov.b64 {%0, %1}, %2;" : "=f"(lo), "=f"(hi) : "l"(v));
}

__device__ __forceinline__ void red_add_v4(float* p, float a, float b, float c, float d) {
    asm volatile("red.global.add.v4.f32 [%0], {%1,%2,%3,%4};"
                 :: "l"(p), "f"(a), "f"(b), "f"(c), "f"(d) : "memory");
}

// ---------------------------------------------------------------------------
// Kernel A: detect edge_index dtype. If int64 (little-endian), the odd 32-bit
// words are high-halves == 0 for indices in [0, 50000). If int32, they are
// random indices — P(256 consecutive odd words all zero) ~ 0.
// ---------------------------------------------------------------------------
__global__ void detect_dtype_kernel(const int* __restrict__ raw) {
    if (threadIdx.x == 0 && blockIdx.x == 0) {
        int any = 0;
        for (int i = 0; i < 256; i++) any |= raw[2 * i + 1];
        d_is64 = (any == 0) ? 1 : 0;
    }
}

// ---------------------------------------------------------------------------
// Kernel B: convert edge_index -> d_src/d_dst (int32) under either dtype.
// Clamp to [0, NN-1]: no-op when detection is right; turns a hypothetical
// mis-detection into a rel_err signal instead of an illegal access.
// ---------------------------------------------------------------------------
__global__ __launch_bounds__(512) void convert_idx_kernel(const void* __restrict__ raw) {
    const int i = blockIdx.x * 512 + threadIdx.x;
    if (i >= 2 * EE) return;
    int v;
    if (d_is64) v = (int)((const long long*)raw)[i];
    else        v = ((const int*)raw)[i];
    v = min(max(v, 0), NN - 1);
    if (i < EE) d_src[i] = v;
    else        d_dst[i - EE] = v;
}

// ---------------------------------------------------------------------------
// Kernel 0: zero agg
// ---------------------------------------------------------------------------
__global__ __launch_bounds__(512) void zero_agg_kernel() {
    int i = blockIdx.x * 512 + threadIdx.x;          // float4 index
    if (i < (NN * HD) / 4) {
        ((float4*)d_agg)[i] = make_float4(0.f, 0.f, 0.f, 0.f);
    }
}

// ---------------------------------------------------------------------------
// Kernel 1: X[n][0:128]   = h[n] @ eW1[0:64]   (src part)
//           X[n][128:256] = h[n] @ eW1[64:128] (dst part)
// 512 threads, 64 nodes per block. f32x2-packed accumulators.
// ---------------------------------------------------------------------------
#define PRE_SMEM ((64*256 + 64*64) * 4)
__global__ __launch_bounds__(512) void precompute_x_kernel(
    const float* __restrict__ h, const float* __restrict__ eW1)
{
    extern __shared__ float sm[];
    float* sW = sm;               // [64][256]
    float* sh = sm + 64 * 256;    // [64][64]
    const int tid = threadIdx.x;
    const int n0 = blockIdx.x * 64;

    for (int p = tid; p < 64 * 256; p += 512) {
        int k = p >> 8, jj = p & 255;
        int row = (jj < 128) ? k : (64 + k);
        sW[p] = eW1[row * 128 + (jj & 127)];
    }
    for (int p = tid; p < 64 * 64; p += 512) {
        int n = p >> 6, c = p & 63;
        int gn = n0 + n;
        sh[p] = (gn < NN) ? h[gn * 64 + c] : 0.f;
    }
    __syncthreads();

    const int ng = tid >> 5;          // 0..15 -> nodes 4*ng..4*ng+3
    const int jg = tid & 31;          // lane  -> cols  8*jg..8*jg+7
    const int nb = ng * 4, jb = jg * 8;

    unsigned long long accp[4][4];
#pragma unroll
    for (int i = 0; i < 4; i++)
#pragma unroll
        for (int q = 0; q < 4; q++) accp[i][q] = 0ull;

#pragma unroll 4
    for (int k = 0; k < 64; k++) {
        ulonglong2 w0 = *(const ulonglong2*)&sW[k * 256 + jb];       // cols jb..jb+3
        ulonglong2 w1 = *(const ulonglong2*)&sW[k * 256 + jb + 4];   // cols jb+4..jb+7
#pragma unroll
        for (int i = 0; i < 4; i++) {
            float hv = sh[(nb + i) * 64 + k];   // broadcast (warp-uniform row)
            unsigned long long hv2; PACK2(hv2, hv);
            FMA2(accp[i][0], hv2, w0.x);
            FMA2(accp[i][1], hv2, w0.y);
            FMA2(accp[i][2], hv2, w1.x);
            FMA2(accp[i][3], hv2, w1.y);
        }
    }
#pragma unroll
    for (int i = 0; i < 4; i++) {
        int gn = n0 + nb + i;
        if (gn < NN) {
            ulonglong2 s0; s0.x = accp[i][0]; s0.y = accp[i][1];
            ulonglong2 s1; s1.x = accp[i][2]; s1.y = accp[i][3];
            *(ulonglong2*)&d_X[gn * 256 + jb]     = s0;
            *(ulonglong2*)&d_X[gn * 256 + jb + 4] = s1;
        }
    }
}

// ---------------------------------------------------------------------------
// Kernel 2 (PERSISTENT): grid-strides over 64-edge tiles.
//   hidden = relu(X[src][0:128] + X[dst][128:256] + edge_attr@W1e + b1)
//   out = hidden @ eW2 + b2 ;  red.v4 into d_agg[dst]
// Weights in smem ONCE per CTA. W2 TRANSPOSED [64 cols][128 k].
// ---------------------------------------------------------------------------
#define ESM_W2T  0                          // 64*WTSTRIDE
#define ESM_W1E  (ESM_W2T + 64*WTSTRIDE)    // 8*128
#define ESM_B1   (ESM_W1E + 8*128)          // 128
#define ESM_B2   (ESM_B1 + 128)             // 64
#define ESM_EA   (ESM_B2 + 64)              // 64*8
#define ESM_HID  (ESM_EA + 64*8)            // 64*HSTRIDE
#define ESM_SRC  (ESM_HID + 64*HSTRIDE)     // 64 (ints)
#define ESM_DST  (ESM_SRC + 64)             // 64 (ints)
#define EDGE_SMEM ((ESM_DST + 64) * 4)

__global__ __launch_bounds__(512) void edge_kernel(
    const float* __restrict__ edge_attr,
    const float* __restrict__ eW1,   // rows 128..135 = W1e
    const float* __restrict__ eb1,
    const float* __restrict__ eW2,
    const float* __restrict__ eb2)
{
    extern __shared__ float sm[];
    float* sW2t = sm + ESM_W2T;
    float* sW1e = sm + ESM_W1E;
    float* sb1  = sm + ESM_B1;
    float* sb2  = sm + ESM_B2;
    float* sEA  = sm + ESM_EA;
    float* sHID = sm + ESM_HID;
    int*   sSRC = (int*)(sm + ESM_SRC);
    int*   sDST = (int*)(sm + ESM_DST);

    const int tid = threadIdx.x;

    // ---- one-time weight setup ----
    for (int p = tid; p < 64 * 128; p += 512) {       // sW2t[c][j] = eW2[j][c]
        int j = p >> 6, c = p & 63;
        sW2t[c * WTSTRIDE + j] = eW2[j * 64 + c];
    }
    for (int p = tid; p < 8 * 128; p += 512)  sW1e[p] = eW1[128 * 128 + p];
    if (tid < 128) sb1[tid] = eb1[tid];
    if (tid < 64)  sb2[tid] = eb2[tid];
    __syncthreads();

    // ---- tile-invariant per-thread state ----
    const int q  = tid & 31;
    const int ew = tid >> 5;
    const ulonglong2 b1q = *(const ulonglong2*)&sb1[q * 4];   // packed bias pairs
    const int eg = tid >> 4;          // 0..31 -> edges 2*eg, 2*eg+1
    const int c0 = (tid & 15) * 4;    // cols c0..c0+3
    const float* hr0 = &sHID[(eg * 2) * HSTRIDE];
    const float* hr1 = hr0 + HSTRIDE;
    const float* w0p = &sW2t[(c0 + 0) * WTSTRIDE];
    const float* w1p = &sW2t[(c0 + 1) * WTSTRIDE];
    const float* w2p = &sW2t[(c0 + 2) * WTSTRIDE];
    const float* w3p = &sW2t[(c0 + 3) * WTSTRIDE];
    const float4 b2v = *(const float4*)&sb2[c0];

    for (int t = blockIdx.x; t < ETILES; t += gridDim.x) {
        const int e0 = t * 64;

        // ---- per-tile loads (indices already int32) ----
        if (tid < 64) {
            sSRC[tid] = d_src[e0 + tid];
            sDST[tid] = d_dst[e0 + tid];
        }
        if (tid >= 64 && tid < 192) {     // 128 threads load 512 attrs (float4)
            int qq = tid - 64;
            *(float4*)&sEA[qq * 4] = *(const float4*)&edge_attr[e0 * 8 + qq * 4];
        }
        __syncthreads();

        // ---- Phase A (f32x2, 4 edges per thread, shared W1e loads) ----
        {
            int e[4];
            unsigned long long h01[4], h23[4];
#pragma unroll
            for (int i = 0; i < 4; i++) {
                e[i] = ew + 16 * i;
                const int src = sSRC[e[i]];               // warp-uniform bcast
                const int dst = sDST[e[i]];
                ulonglong2 a = *(const ulonglong2*)&d_X[src * 256 + q * 4];
                ulonglong2 b = *(const ulonglong2*)&d_X[dst * 256 + 128 + q * 4];
                ADD2(h01[i], a.x, b.x); ADD2(h01[i], h01[i], b1q.x);
                ADD2(h23[i], a.y, b.y); ADD2(h23[i], h23[i], b1q.y);
            }
#pragma unroll
            for (int k = 0; k < 8; k++) {
                ulonglong2 w = *(const ulonglong2*)&sW1e[k * 128 + q * 4]; // 1 LDS.128 / 8 FMA2
#pragma unroll
                for (int i = 0; i < 4; i++) {
                    float ev = sEA[e[i] * 8 + k];         // warp-uniform bcast
                    unsigned long long ev2; PACK2(ev2, ev);
                    FMA2(h01[i], ev2, w.x);
                    FMA2(h23[i], ev2, w.y);
                }
            }
#pragma unroll
            for (int i = 0; i < 4; i++) {
                float f0, f1, f2, f3;
                unpack2(h01[i], f0, f1);
                unpack2(h23[i], f2, f3);
                float4 r = make_float4(fmaxf(f0, 0.f), fmaxf(f1, 0.f),
                                       fmaxf(f2, 0.f), fmaxf(f3, 0.f));
                *(float4*)&sHID[e[i] * HSTRIDE + q * 4] = r;
            }
        }
        __syncthreads();

        // ---- Phase B (f32x2 packed): out[e][c] = hidden[e] @ W2 + b2 ----
        unsigned long long p00 = 0, p01 = 0, p02 = 0, p03 = 0;
        unsigned long long p10 = 0, p11 = 0, p12 = 0, p13 = 0;
#pragma unroll 2
        for (int j = 0; j < 128; j += 4) {
            ulonglong2 h0 = *(const ulonglong2*)&hr0[j];
            ulonglong2 h1 = *(const ulonglong2*)&hr1[j];
            ulonglong2 w0 = *(const ulonglong2*)&w0p[j];
            ulonglong2 w1 = *(const ulonglong2*)&w1p[j];
            ulonglong2 w2 = *(const ulonglong2*)&w2p[j];
            ulonglong2 w3 = *(const ulonglong2*)&w3p[j];
            FMA2(p00, h0.x, w0.x); FMA2(p00, h0.y, w0.y);
            FMA2(p01, h0.x, w1.x); FMA2(p01, h0.y, w1.y);
            FMA2(p02, h0.x, w2.x); FMA2(p02, h0.y, w2.y);
            FMA2(p03, h0.x, w3.x); FMA2(p03, h0.y, w3.y);
            FMA2(p10, h1.x, w0.x); FMA2(p10, h1.y, w0.y);
            FMA2(p11, h1.x, w1.x); FMA2(p11, h1.y, w1.y);
            FMA2(p12, h1.x, w2.x); FMA2(p12, h1.y, w2.y);
            FMA2(p13, h1.x, w3.x); FMA2(p13, h1.y, w3.y);
        }
        const int d0 = sDST[eg * 2];
        const int d1 = sDST[eg * 2 + 1];
        red_add_v4(&d_agg[d0 * 64 + c0],
                   hadd_f32x2(p00) + b2v.x, hadd_f32x2(p01) + b2v.y,
                   hadd_f32x2(p02) + b2v.z, hadd_f32x2(p03) + b2v.w);
        red_add_v4(&d_agg[d1 * 64 + c0],
                   hadd_f32x2(p10) + b2v.x, hadd_f32x2(p11) + b2v.y,
                   hadd_f32x2(p12) + b2v.z, hadd_f32x2(p13) + b2v.w);
        __syncthreads();   // protect sEA/sSRC/sDST/sHID before next tile
    }
}

// ---------------------------------------------------------------------------
// Kernel 3 (PERSISTENT): grid-strides over 32-node tiles.
// node update MLP + residual + LayerNorm. W1/W2 TRANSPOSED ([col][k]).
// ---------------------------------------------------------------------------
#define NSM_W1T  0                          // 128*WTSTRIDE
#define NSM_W2T  (NSM_W1T + 128*WTSTRIDE)   // 64*WTSTRIDE
#define NSM_U    (NSM_W2T + 64*WTSTRIDE)    // 32*HSTRIDE (u_in; reused as res[32][RSTRIDE])
#define NSM_H2   (NSM_U + 32*HSTRIDE)       // 32*HSTRIDE
#define NSM_B1   (NSM_H2 + 32*HSTRIDE)      // 128
#define NSM_B2   (NSM_B1 + 128)             // 64
#define NSM_LG   (NSM_B2 + 64)              // 64
#define NSM_LB   (NSM_LG + 64)              // 64
#define NODE_SMEM ((NSM_LB + 64) * 4)

__global__ __launch_bounds__(512) void node_kernel(
    const float* __restrict__ h,
    const float* __restrict__ nW1, const float* __restrict__ nb1,
    const float* __restrict__ nW2, const float* __restrict__ nb2,
    const float* __restrict__ ln_g, const float* __restrict__ ln_b,
    float* __restrict__ out)
{
    extern __shared__ float sm[];
    float* sW1t = sm + NSM_W1T;
    float* sW2t = sm + NSM_W2T;
    float* sU   = sm + NSM_U;
    float* sH2  = sm + NSM_H2;
    float* sb1  = sm + NSM_B1;
    float* sb2  = sm + NSM_B2;
    float* sLG  = sm + NSM_LG;
    float* sLB  = sm + NSM_LB;

    const int tid = threadIdx.x;

    // ---- one-time weight setup ----
    for (int p = tid; p < 128 * 128; p += 512) {      // sW1t[j][k] = nW1[k][j]
        int k = p >> 7, j = p & 127;
        sW1t[j * WTSTRIDE + k] = nW1[p];
    }
    for (int p = tid; p < 64 * 128; p += 512) {       // sW2t[c][j] = nW2[j][c]
        int j = p >> 6, c = p & 63;
        sW2t[c * WTSTRIDE + j] = nW2[p];
    }
    if (tid < 128) sb1[tid] = nb1[tid];
    if (tid < 64)  sb2[tid] = nb2[tid];
    if (tid >= 64 && tid < 128)  sLG[tid - 64] = ln_g[tid - 64];
    if (tid >= 128 && tid < 192) sLB[tid - 128] = ln_b[tid - 128];

    for (int t = blockIdx.x; t < NTILES; t += gridDim.x) {
        const int n0 = t * 32;

        for (int p = tid; p < 32 * 128; p += 512) {
            int n = p >> 7, c = p & 127;
            int gn = n0 + n;
            float v = 0.f;
            if (gn < NN) v = (c < 64) ? h[gn * 64 + c] : d_agg[gn * 64 + (c - 64)];
            sU[n * HSTRIDE + c] = v;
        }
        __syncthreads();

        // ---- layer 1 (f32x2): hid[n][j] = relu(u_in[n] @ W1 + b1) ----
        {
            const int ng = tid >> 5;       // 0..15 -> nodes 2*ng, 2*ng+1
            const int j0 = (tid & 31) * 4;
            const float* u0 = &sU[(ng * 2) * HSTRIDE];
            const float* u1 = u0 + HSTRIDE;
            const float* w0p = &sW1t[(j0 + 0) * WTSTRIDE];
            const float* w1p = &sW1t[(j0 + 1) * WTSTRIDE];
            const float* w2p = &sW1t[(j0 + 2) * WTSTRIDE];
            const float* w3p = &sW1t[(j0 + 3) * WTSTRIDE];

            unsigned long long p00 = 0, p01 = 0, p02 = 0, p03 = 0;
            unsigned long long p10 = 0, p11 = 0, p12 = 0, p13 = 0;
#pragma unroll 2
            for (int k = 0; k < 128; k += 4) {
                ulonglong2 v0 = *(const ulonglong2*)&u0[k];
                ulonglong2 v1 = *(const ulonglong2*)&u1[k];
                ulonglong2 w0 = *(const ulonglong2*)&w0p[k];
                ulonglong2 w1 = *(const ulonglong2*)&w1p[k];
                ulonglong2 w2 = *(const ulonglong2*)&w2p[k];
                ulonglong2 w3 = *(const ulonglong2*)&w3p[k];
                FMA2(p00, v0.x, w0.x); FMA2(p00, v0.y, w0.y);
                FMA2(p01, v0.x, w1.x); FMA2(p01, v0.y, w1.y);
                FMA2(p02, v0.x, w2.x); FMA2(p02, v0.y, w2.y);
                FMA2(p03, v0.x, w3.x); FMA2(p03, v0.y, w3.y);
                FMA2(p10, v1.x, w0.x); FMA2(p10, v1.y, w0.y);
                FMA2(p11, v1.x, w1.x); FMA2(p11, v1.y, w1.y);
                FMA2(p12, v1.x, w2.x); FMA2(p12, v1.y, w2.y);
                FMA2(p13, v1.x, w3.x); FMA2(p13, v1.y, w3.y);
            }
            float4 bs = *(const float4*)&sb1[j0];
            float4 r0 = make_float4(fmaxf(hadd_f32x2(p00) + bs.x, 0.f),
                                    fmaxf(hadd_f32x2(p01) + bs.y, 0.f),
                                    fmaxf(hadd_f32x2(p02) + bs.z, 0.f),
                                    fmaxf(hadd_f32x2(p03) + bs.w, 0.f));
            float4 r1 = make_float4(fmaxf(hadd_f32x2(p10) + bs.x, 0.f),
                                    fmaxf(hadd_f32x2(p11) + bs.y, 0.f),
                                    fmaxf(hadd_f32x2(p12) + bs.z, 0.f),
                                    fmaxf(hadd_f32x2(p13) + bs.w, 0.f));
            *(float4*)&sH2[(ng * 2) * HSTRIDE + j0]     = r0;
            *(float4*)&sH2[(ng * 2 + 1) * HSTRIDE + j0] = r1;
        }
        __syncthreads();

        // ---- layer 2 + residual (f32x2): res = hid@W2 + b2 + h ----
        {
            const int nn = tid >> 4;       // 0..31
            const int c0 = (tid & 15) * 4;
            const float* hv = &sH2[nn * HSTRIDE];
            const float* w0p = &sW2t[(c0 + 0) * WTSTRIDE];
            const float* w1p = &sW2t[(c0 + 1) * WTSTRIDE];
            const float* w2p = &sW2t[(c0 + 2) * WTSTRIDE];
            const float* w3p = &sW2t[(c0 + 3) * WTSTRIDE];

            unsigned long long p0 = 0, p1 = 0, p2 = 0, p3 = 0;
#pragma unroll 2
            for (int j = 0; j < 128; j += 4) {
                ulonglong2 hj = *(const ulonglong2*)&hv[j];
                ulonglong2 w0 = *(const ulonglong2*)&w0p[j];
                ulonglong2 w1 = *(const ulonglong2*)&w1p[j];
                ulonglong2 w2 = *(const ulonglong2*)&w2p[j];
                ulonglong2 w3 = *(const ulonglong2*)&w3p[j];
                FMA2(p0, hj.x, w0.x); FMA2(p0, hj.y, w0.y);
                FMA2(p1, hj.x, w1.x); FMA2(p1, hj.y, w1.y);
                FMA2(p2, hj.x, w2.x); FMA2(p2, hj.y, w2.y);
                FMA2(p3, hj.x, w3.x); FMA2(p3, hj.y, w3.y);
            }
            float4 bs = *(const float4*)&sb2[c0];
            const int gn = t * 32 + nn;
            float4 r = make_float4(0.f, 0.f, 0.f, 0.f);
            if (gn < NN) {
                float4 hres = *(const float4*)&h[gn * 64 + c0];
                r = make_float4(hadd_f32x2(p0) + bs.x + hres.x,
                                hadd_f32x2(p1) + bs.y + hres.y,
                                hadd_f32x2(p2) + bs.z + hres.z,
                                hadd_f32x2(p3) + bs.w + hres.w);
            }
            __syncthreads();                      // sU u_in no longer needed
            *(float4*)&sU[nn * RSTRIDE + c0] = r; // reuse sU as res[32][RSTRIDE]
        }
        __syncthreads();

        // ---- LayerNorm over 64 dims, one warp per 2 nodes ----
        {
            const int wid = tid >> 5;      // 0..15
            const int lane = tid & 31;
#pragma unroll
            for (int s = 0; s < 2; s++) {
                const int n = wid * 2 + s;
                const int gn = t * 32 + n;
                if (gn >= NN) continue;
                float v0 = sU[n * RSTRIDE + lane];
                float v1 = sU[n * RSTRIDE + 32 + lane];
                float sum = v0 + v1;
                float sq  = v0 * v0 + v1 * v1;
#pragma unroll
                for (int o = 16; o > 0; o >>= 1) {
                    sum += __shfl_xor_sync(0xFFFFFFFFu, sum, o);
                    sq  += __shfl_xor_sync(0xFFFFFFFFu, sq, o);
                }
                float mean = sum * (1.f / 64.f);
                float var  = sq * (1.f / 64.f) - mean * mean;
                float rstd = rsqrtf(var + LN_EPS);
                out[gn * 64 + lane]      = (v0 - mean) * rstd * sLG[lane] + sLB[lane];
                out[gn * 64 + 32 + lane] = (v1 - mean) * rstd * sLG[32 + lane] + sLB[32 + lane];
            }
        }
        __syncthreads();   // protect sU before next tile's u_in load
    }
}

// ---------------------------------------------------------------------------
extern "C" void kernel_launch(void* const* d_in, const int* in_sizes, int n_in,
                              void* d_out, int out_size)
{
    const float* h    = (const float*)d_in[0];
    const void*  eidx = d_in[1];                 // int32 or int64 — detected on device
    const float* ea   = (const float*)d_in[2];
    const float* eW1  = (const float*)d_in[3];
    const float* eb1  = (const float*)d_in[4];
    const float* eW2  = (const float*)d_in[5];
    const float* eb2  = (const float*)d_in[6];
    const float* nW1  = (const float*)d_in[7];
    const float* nb1  = (const float*)d_in[8];
    const float* nW2  = (const float*)d_in[9];
    const float* nb2  = (const float*)d_in[10];
    const float* lng  = (const float*)d_in[11];
    const float* lnb  = (const float*)d_in[12];
    float* out = (float*)d_out;

    cudaFuncSetAttribute(precompute_x_kernel,
                         cudaFuncAttributeMaxDynamicSharedMemorySize, PRE_SMEM);
    cudaFuncSetAttribute(edge_kernel,
                         cudaFuncAttributeMaxDynamicSharedMemorySize, EDGE_SMEM);
    cudaFuncSetAttribute(node_kernel,
                         cudaFuncAttributeMaxDynamicSharedMemorySize, NODE_SMEM);

    detect_dtype_kernel<<<1, 32>>>((const int*)eidx);
    convert_idx_kernel<<<(2 * EE + 511) / 512, 512>>>(eidx);
    zero_agg_kernel<<<(NN * HD / 4 + 511) / 512, 512>>>();
    precompute_x_kernel<<<(NN + 63) / 64, 512, PRE_SMEM>>>(h, eW1);
    edge_kernel<<<444, 512, EDGE_SMEM>>>(ea, eW1, eb1, eW2, eb2);
    node_kernel<<<148, 512, NODE_SMEM>>>(h, nW1, nb1, nW2, nb2,
                                         lng, lnb, out);
}

// round 13
// speedup vs baseline: 2.2057x; 2.2057x over previous
#include <cuda_runtime.h>

#define NN 50000
#define EE 800000
#define HD 64
#define ED 8
#define LN_EPS 1e-5f
#define ETILES (EE / 64)            // 12500
#define NTILES ((NN + 31) / 32)     // 1563

#define HSTRIDE 132      // 128-wide rows (u_in / hid in node kernel)
#define H2STRIDE 260     // duplicated-pair hid rows: 128*2 + 4 pad (1040B, 16B-aligned)
#define RSTRIDE 68       // 64-wide rows

// Scratch (static device arrays: allocation-free rule)
__device__ float d_X[NN * 256];     // [Xs(128) | Xd(128)] per node = h@W1s | h@W1d
__device__ float d_agg[NN * HD];    // scatter-add destination
__device__ int   d_src[EE];         // edge sources (int32, post-conversion)
__device__ int   d_dst[EE];         // edge destinations
__device__ int   d_is64;            // 1 if edge_index buffer is int64

// ---- packed f32x2 helpers (Blackwell FFMA2; only reachable via PTX) ----
#define FMA2(acc, a, b) \
    asm("fma.rn.f32x2 %0, %1, %2, %0;" : "+l"(acc) : "l"(a), "l"(b))
#define ADD2(d, a, b) \
    asm("add.rn.f32x2 %0, %1, %2;" : "=l"(d) : "l"(a), "l"(b))
#define PACK2(d, s) \
    asm("mov.b64 %0, {%1, %1};" : "=l"(d) : "f"(s))

__device__ __forceinline__ void unpack2(unsigned long long v, float& lo, float& hi) {
    asm("mov.b64 {%0, %1}, %2;" : "=f"(lo), "=f"(hi) : "l"(v));
}

__device__ __forceinline__ void red_add_v4(float* p, float a, float b, float c, float d) {
    asm volatile("red.global.add.v4.f32 [%0], {%1,%2,%3,%4};"
                 :: "l"(p), "f"(a), "f"(b), "f"(c), "f"(d) : "memory");
}

// ---------------------------------------------------------------------------
// Kernel A: detect edge_index dtype (int64 -> odd 32-bit words all zero).
// ---------------------------------------------------------------------------
__global__ void detect_dtype_kernel(const int* __restrict__ raw) {
    if (threadIdx.x == 0 && blockIdx.x == 0) {
        int any = 0;
        for (int i = 0; i < 256; i++) any |= raw[2 * i + 1];
        d_is64 = (any == 0) ? 1 : 0;
    }
}

// ---------------------------------------------------------------------------
// Kernel B: convert edge_index -> d_src/d_dst (int32), clamped.
// ---------------------------------------------------------------------------
__global__ __launch_bounds__(512) void convert_idx_kernel(const void* __restrict__ raw) {
    const int i = blockIdx.x * 512 + threadIdx.x;
    if (i >= 2 * EE) return;
    int v;
    if (d_is64) v = (int)((const long long*)raw)[i];
    else        v = ((const int*)raw)[i];
    v = min(max(v, 0), NN - 1);
    if (i < EE) d_src[i] = v;
    else        d_dst[i - EE] = v;
}

// ---------------------------------------------------------------------------
// Kernel 0: zero agg
// ---------------------------------------------------------------------------
__global__ __launch_bounds__(512) void zero_agg_kernel() {
    int i = blockIdx.x * 512 + threadIdx.x;
    if (i < (NN * HD) / 4) {
        ((float4*)d_agg)[i] = make_float4(0.f, 0.f, 0.f, 0.f);
    }
}

// ---------------------------------------------------------------------------
// Kernel 1: X[n][0:128] = h[n]@eW1[0:64]; X[n][128:256] = h[n]@eW1[64:128]
// 512 threads, 64 nodes/block. Weights c-major in smem (conflict-free).
// ---------------------------------------------------------------------------
#define PRE_SMEM ((64*256 + 64*64) * 4)
__global__ __launch_bounds__(512) void precompute_x_kernel(
    const float* __restrict__ h, const float* __restrict__ eW1)
{
    extern __shared__ float sm[];
    float* sW = sm;               // [64][256]
    float* sh = sm + 64 * 256;    // [64][64]
    const int tid = threadIdx.x;
    const int n0 = blockIdx.x * 64;

    for (int p = tid; p < 64 * 256; p += 512) {
        int k = p >> 8, jj = p & 255;
        int row = (jj < 128) ? k : (64 + k);
        sW[p] = eW1[row * 128 + (jj & 127)];
    }
    for (int p = tid; p < 64 * 64; p += 512) {
        int n = p >> 6, c = p & 63;
        int gn = n0 + n;
        sh[p] = (gn < NN) ? h[gn * 64 + c] : 0.f;
    }
    __syncthreads();

    const int ng = tid >> 5;          // 0..15 -> nodes 4*ng..4*ng+3
    const int jg = tid & 31;          // lane  -> cols  8*jg..8*jg+7
    const int nb = ng * 4, jb = jg * 8;

    unsigned long long accp[4][4];
#pragma unroll
    for (int i = 0; i < 4; i++)
#pragma unroll
        for (int q = 0; q < 4; q++) accp[i][q] = 0ull;

#pragma unroll 4
    for (int k = 0; k < 64; k++) {
        ulonglong2 w0 = *(const ulonglong2*)&sW[k * 256 + jb];
        ulonglong2 w1 = *(const ulonglong2*)&sW[k * 256 + jb + 4];
#pragma unroll
        for (int i = 0; i < 4; i++) {
            float hv = sh[(nb + i) * 64 + k];   // broadcast
            unsigned long long hv2; PACK2(hv2, hv);
            FMA2(accp[i][0], hv2, w0.x);
            FMA2(accp[i][1], hv2, w0.y);
            FMA2(accp[i][2], hv2, w1.x);
            FMA2(accp[i][3], hv2, w1.y);
        }
    }
#pragma unroll
    for (int i = 0; i < 4; i++) {
        int gn = n0 + nb + i;
        if (gn < NN) {
            ulonglong2 s0; s0.x = accp[i][0]; s0.y = accp[i][1];
            ulonglong2 s1; s1.x = accp[i][2]; s1.y = accp[i][3];
            *(ulonglong2*)&d_X[gn * 256 + jb]     = s0;
            *(ulonglong2*)&d_X[gn * 256 + jb + 4] = s1;
        }
    }
}

// ---------------------------------------------------------------------------
// Kernel 2 (PERSISTENT): 64-edge tiles.
//   Phase A: hidden = relu(X[src][0:128] + X[dst][128:256] + ea@W1e + b1),
//            stored DUPLICATED ((h,h) pairs) for Phase B packed broadcasts.
//   Phase B: out = hidden @ W2 + b2 (W2 c-major, conflict-free; col-packed
//            FMA2 accumulators = complete dot products, no hadd), red.v4.
// ---------------------------------------------------------------------------
#define ESM_W2   0                          // 128*64 (row-major, as input)
#define ESM_W1E  (ESM_W2 + 128*64)          // 8*128
#define ESM_B1   (ESM_W1E + 8*128)          // 128
#define ESM_B2   (ESM_B1 + 128)             // 64
#define ESM_EA   (ESM_B2 + 64)              // 64*8
#define ESM_HID2 (ESM_EA + 64*8)            // 64*H2STRIDE (duplicated pairs)
#define ESM_SRC  (ESM_HID2 + 64*H2STRIDE)   // 64 (ints)
#define ESM_DST  (ESM_SRC + 64)             // 64 (ints)
#define EDGE_SMEM ((ESM_DST + 64) * 4)      // ~104 KB -> 2 CTAs/SM

__global__ __launch_bounds__(512) void edge_kernel(
    const float* __restrict__ edge_attr,
    const float* __restrict__ eW1,   // rows 128..135 = W1e
    const float* __restrict__ eb1,
    const float* __restrict__ eW2,
    const float* __restrict__ eb2)
{
    extern __shared__ float sm[];
    float* sW2  = sm + ESM_W2;
    float* sW1e = sm + ESM_W1E;
    float* sb1  = sm + ESM_B1;
    float* sb2  = sm + ESM_B2;
    float* sEA  = sm + ESM_EA;
    float* sH2d = sm + ESM_HID2;
    int*   sSRC = (int*)(sm + ESM_SRC);
    int*   sDST = (int*)(sm + ESM_DST);

    const int tid = threadIdx.x;

    // ---- one-time weight setup (no transpose: natural layouts) ----
    for (int p = tid; p < 128 * 64; p += 512) sW2[p] = eW2[p];
    for (int p = tid; p < 8 * 128; p += 512)  sW1e[p] = eW1[128 * 128 + p];
    if (tid < 128) sb1[tid] = eb1[tid];
    if (tid < 64)  sb2[tid] = eb2[tid];
    __syncthreads();

    // ---- tile-invariant per-thread state ----
    // Phase A: q = column quad (0..31), ew = warp id -> edges ew+16i
    const int q  = tid & 31;
    const int ew = tid >> 5;
    const ulonglong2 b1q = *(const ulonglong2*)&sb1[q * 4];
    // Phase B: 2 edges x 4 cols
    const int eg = tid >> 4;          // 0..31 -> edges 2*eg, 2*eg+1
    const int c0 = (tid & 15) * 4;    // cols c0..c0+3 (lanes consecutive)
    const float* h0p = &sH2d[(eg * 2) * H2STRIDE];
    const float* h1p = h0p + H2STRIDE;
    const float4 b2v = *(const float4*)&sb2[c0];

    for (int t = blockIdx.x; t < ETILES; t += gridDim.x) {
        const int e0 = t * 64;

        if (tid < 64) {
            sSRC[tid] = d_src[e0 + tid];
            sDST[tid] = d_dst[e0 + tid];
        }
        if (tid >= 64 && tid < 192) {
            int qq = tid - 64;
            *(float4*)&sEA[qq * 4] = *(const float4*)&edge_attr[e0 * 8 + qq * 4];
        }
        __syncthreads();

        // ---- Phase A (f32x2, 4 edges per thread, shared W1e loads) ----
        {
            int e[4];
            unsigned long long h01[4], h23[4];
#pragma unroll
            for (int i = 0; i < 4; i++) {
                e[i] = ew + 16 * i;
                const int src = sSRC[e[i]];
                const int dst = sDST[e[i]];
                ulonglong2 a = *(const ulonglong2*)&d_X[src * 256 + q * 4];
                ulonglong2 b = *(const ulonglong2*)&d_X[dst * 256 + 128 + q * 4];
                ADD2(h01[i], a.x, b.x); ADD2(h01[i], h01[i], b1q.x);
                ADD2(h23[i], a.y, b.y); ADD2(h23[i], h23[i], b1q.y);
            }
#pragma unroll
            for (int k = 0; k < 8; k++) {
                ulonglong2 w = *(const ulonglong2*)&sW1e[k * 128 + q * 4];
#pragma unroll
                for (int i = 0; i < 4; i++) {
                    float ev = sEA[e[i] * 8 + k];
                    unsigned long long ev2; PACK2(ev2, ev);
                    FMA2(h01[i], ev2, w.x);
                    FMA2(h23[i], ev2, w.y);
                }
            }
#pragma unroll
            for (int i = 0; i < 4; i++) {
                float f0, f1, f2, f3;
                unpack2(h01[i], f0, f1);
                unpack2(h23[i], f2, f3);
                f0 = fmaxf(f0, 0.f); f1 = fmaxf(f1, 0.f);
                f2 = fmaxf(f2, 0.f); f3 = fmaxf(f3, 0.f);
                // duplicated-pair store: (f0,f0,f1,f1),(f2,f2,f3,f3)
                *(float4*)&sH2d[e[i] * H2STRIDE + q * 8]     = make_float4(f0, f0, f1, f1);
                *(float4*)&sH2d[e[i] * H2STRIDE + q * 8 + 4] = make_float4(f2, f2, f3, f3);
            }
        }
        __syncthreads();

        // ---- Phase B: col-packed FMA2, conflict-free weights ----
        unsigned long long pA0 = 0, pA1 = 0, pB0 = 0, pB1 = 0;
#pragma unroll 4
        for (int j = 0; j < 128; j += 2) {
            ulonglong2 hh0 = *(const ulonglong2*)&h0p[j * 2];   // ((h[j],h[j]),(h[j+1],h[j+1]))
            ulonglong2 hh1 = *(const ulonglong2*)&h1p[j * 2];
            ulonglong2 w0  = *(const ulonglong2*)&sW2[j * 64 + c0];       // row j cols c0..c0+3
            ulonglong2 w1  = *(const ulonglong2*)&sW2[(j + 1) * 64 + c0];
            FMA2(pA0, hh0.x, w0.x); FMA2(pA1, hh0.x, w0.y);
            FMA2(pB0, hh1.x, w0.x); FMA2(pB1, hh1.x, w0.y);
            FMA2(pA0, hh0.y, w1.x); FMA2(pA1, hh0.y, w1.y);
            FMA2(pB0, hh1.y, w1.x); FMA2(pB1, hh1.y, w1.y);
        }
        float a0, a1, a2, a3, b0, b1, b2s, b3;
        unpack2(pA0, a0, a1); unpack2(pA1, a2, a3);
        unpack2(pB0, b0, b1); unpack2(pB1, b2s, b3);
        const int d0 = sDST[eg * 2];
        const int d1 = sDST[eg * 2 + 1];
        red_add_v4(&d_agg[d0 * 64 + c0], a0 + b2v.x, a1 + b2v.y, a2 + b2v.z, a3 + b2v.w);
        red_add_v4(&d_agg[d1 * 64 + c0], b0 + b2v.x, b1 + b2v.y, b2s + b2v.z, b3 + b2v.w);
        __syncthreads();   // protect smem before next tile
    }
}

// ---------------------------------------------------------------------------
// Kernel 3 (PERSISTENT): 32-node tiles. Weights in NATURAL layouts
// (conflict-free lanes-consecutive loads); col-packed FMA2.
// ---------------------------------------------------------------------------
#define NSM_W1   0                          // 128*128 (row-major [k][j])
#define NSM_W2   (NSM_W1 + 128*128)         // 128*64  (row-major [j][c])
#define NSM_U    (NSM_W2 + 128*64)          // 32*HSTRIDE (u_in; reused as res[32][RSTRIDE])
#define NSM_H2   (NSM_U + 32*HSTRIDE)       // 32*HSTRIDE
#define NSM_B1   (NSM_H2 + 32*HSTRIDE)      // 128
#define NSM_B2   (NSM_B1 + 128)             // 64
#define NSM_LG   (NSM_B2 + 64)              // 64
#define NSM_LB   (NSM_LG + 64)              // 64
#define NODE_SMEM ((NSM_LB + 64) * 4)       // ~130 KB -> 1 CTA/SM

__global__ __launch_bounds__(512) void node_kernel(
    const float* __restrict__ h,
    const float* __restrict__ nW1, const float* __restrict__ nb1,
    const float* __restrict__ nW2, const float* __restrict__ nb2,
    const float* __restrict__ ln_g, const float* __restrict__ ln_b,
    float* __restrict__ out)
{
    extern __shared__ float sm[];
    float* sW1 = sm + NSM_W1;
    float* sW2 = sm + NSM_W2;
    float* sU  = sm + NSM_U;
    float* sH2 = sm + NSM_H2;
    float* sb1 = sm + NSM_B1;
    float* sb2 = sm + NSM_B2;
    float* sLG = sm + NSM_LG;
    float* sLB = sm + NSM_LB;

    const int tid = threadIdx.x;

    for (int p = tid; p < 128 * 128; p += 512) sW1[p] = nW1[p];
    for (int p = tid; p < 128 * 64; p += 512)  sW2[p] = nW2[p];
    if (tid < 128) sb1[tid] = nb1[tid];
    if (tid < 64)  sb2[tid] = nb2[tid];
    if (tid >= 64 && tid < 128)  sLG[tid - 64] = ln_g[tid - 64];
    if (tid >= 128 && tid < 192) sLB[tid - 128] = ln_b[tid - 128];

    for (int t = blockIdx.x; t < NTILES; t += gridDim.x) {
        const int n0 = t * 32;

        for (int p = tid; p < 32 * 128; p += 512) {
            int n = p >> 7, c = p & 127;
            int gn = n0 + n;
            float v = 0.f;
            if (gn < NN) v = (c < 64) ? h[gn * 64 + c] : d_agg[gn * 64 + (c - 64)];
            sU[n * HSTRIDE + c] = v;
        }
        __syncthreads();

        // ---- layer 1: hid[n][j] = relu(u@W1 + b1); thread = 2 nodes x 4 j ----
        {
            const int ng = tid >> 5;           // nodes 2ng, 2ng+1
            const int j0 = (tid & 31) * 4;     // lanes consecutive -> conflict-free
            const float* u0 = &sU[(ng * 2) * HSTRIDE];
            const float* u1 = u0 + HSTRIDE;
            unsigned long long q01 = 0, q23 = 0, r01 = 0, r23 = 0;
#pragma unroll 4
            for (int k = 0; k < 128; k += 4) {
                float4 av = *(const float4*)&u0[k];   // broadcast
                float4 bv = *(const float4*)&u1[k];
                ulonglong2 w0 = *(const ulonglong2*)&sW1[(k + 0) * 128 + j0];
                ulonglong2 w1 = *(const ulonglong2*)&sW1[(k + 1) * 128 + j0];
                ulonglong2 w2 = *(const ulonglong2*)&sW1[(k + 2) * 128 + j0];
                ulonglong2 w3 = *(const ulonglong2*)&sW1[(k + 3) * 128 + j0];
                unsigned long long ua, ub;
                PACK2(ua, av.x); PACK2(ub, bv.x);
                FMA2(q01, ua, w0.x); FMA2(q23, ua, w0.y);
                FMA2(r01, ub, w0.x); FMA2(r23, ub, w0.y);
                PACK2(ua, av.y); PACK2(ub, bv.y);
                FMA2(q01, ua, w1.x); FMA2(q23, ua, w1.y);
                FMA2(r01, ub, w1.x); FMA2(r23, ub, w1.y);
                PACK2(ua, av.z); PACK2(ub, bv.z);
                FMA2(q01, ua, w2.x); FMA2(q23, ua, w2.y);
                FMA2(r01, ub, w2.x); FMA2(r23, ub, w2.y);
                PACK2(ua, av.w); PACK2(ub, bv.w);
                FMA2(q01, ua, w3.x); FMA2(q23, ua, w3.y);
                FMA2(r01, ub, w3.x); FMA2(r23, ub, w3.y);
            }
            float4 bs = *(const float4*)&sb1[j0];
            float x0, x1, x2, x3;
            unpack2(q01, x0, x1); unpack2(q23, x2, x3);
            *(float4*)&sH2[(ng * 2) * HSTRIDE + j0] =
                make_float4(fmaxf(x0 + bs.x, 0.f), fmaxf(x1 + bs.y, 0.f),
                            fmaxf(x2 + bs.z, 0.f), fmaxf(x3 + bs.w, 0.f));
            unpack2(r01, x0, x1); unpack2(r23, x2, x3);
            *(float4*)&sH2[(ng * 2 + 1) * HSTRIDE + j0] =
                make_float4(fmaxf(x0 + bs.x, 0.f), fmaxf(x1 + bs.y, 0.f),
                            fmaxf(x2 + bs.z, 0.f), fmaxf(x3 + bs.w, 0.f));
        }
        __syncthreads();

        // ---- layer 2 + residual: thread = 1 node x 4 cols ----
        {
            const int nn = tid >> 4;           // 0..31
            const int c0 = (tid & 15) * 4;
            const float* hv = &sH2[nn * HSTRIDE];
            unsigned long long s01 = 0, s23 = 0;
#pragma unroll 4
            for (int j = 0; j < 128; j += 4) {
                float4 hj = *(const float4*)&hv[j];   // broadcast
                ulonglong2 w0 = *(const ulonglong2*)&sW2[(j + 0) * 64 + c0];
                ulonglong2 w1 = *(const ulonglong2*)&sW2[(j + 1) * 64 + c0];
                ulonglong2 w2 = *(const ulonglong2*)&sW2[(j + 2) * 64 + c0];
                ulonglong2 w3 = *(const ulonglong2*)&sW2[(j + 3) * 64 + c0];
                unsigned long long hp;
                PACK2(hp, hj.x); FMA2(s01, hp, w0.x); FMA2(s23, hp, w0.y);
                PACK2(hp, hj.y); FMA2(s01, hp, w1.x); FMA2(s23, hp, w1.y);
                PACK2(hp, hj.z); FMA2(s01, hp, w2.x); FMA2(s23, hp, w2.y);
                PACK2(hp, hj.w); FMA2(s01, hp, w3.x); FMA2(s23, hp, w3.y);
            }
            float4 bs = *(const float4*)&sb2[c0];
            const int gn = t * 32 + nn;
            float4 r = make_float4(0.f, 0.f, 0.f, 0.f);
            if (gn < NN) {
                float4 hres = *(const float4*)&h[gn * 64 + c0];
                float y0, y1, y2, y3;
                unpack2(s01, y0, y1); unpack2(s23, y2, y3);
                r = make_float4(y0 + bs.x + hres.x, y1 + bs.y + hres.y,
                                y2 + bs.z + hres.z, y3 + bs.w + hres.w);
            }
            *(float4*)&sU[nn * RSTRIDE + c0] = r;   // reuse sU as res[32][RSTRIDE]
        }
        __syncthreads();

        // ---- LayerNorm over 64 dims, one warp per 2 nodes ----
        {
            const int wid = tid >> 5;
            const int lane = tid & 31;
#pragma unroll
            for (int s = 0; s < 2; s++) {
                const int n = wid * 2 + s;
                const int gn = t * 32 + n;
                if (gn >= NN) continue;
                float v0 = sU[n * RSTRIDE + lane];
                float v1 = sU[n * RSTRIDE + 32 + lane];
                float sum = v0 + v1;
                float sq  = v0 * v0 + v1 * v1;
#pragma unroll
                for (int o = 16; o > 0; o >>= 1) {
                    sum += __shfl_xor_sync(0xFFFFFFFFu, sum, o);
                    sq  += __shfl_xor_sync(0xFFFFFFFFu, sq, o);
                }
                float mean = sum * (1.f / 64.f);
                float var  = sq * (1.f / 64.f) - mean * mean;
                float rstd = rsqrtf(var + LN_EPS);
                out[gn * 64 + lane]      = (v0 - mean) * rstd * sLG[lane] + sLB[lane];
                out[gn * 64 + 32 + lane] = (v1 - mean) * rstd * sLG[32 + lane] + sLB[32 + lane];
            }
        }
        __syncthreads();
    }
}

// ---------------------------------------------------------------------------
extern "C" void kernel_launch(void* const* d_in, const int* in_sizes, int n_in,
                              void* d_out, int out_size)
{
    const float* h    = (const float*)d_in[0];
    const void*  eidx = d_in[1];
    const float* ea   = (const float*)d_in[2];
    const float* eW1  = (const float*)d_in[3];
    const float* eb1  = (const float*)d_in[4];
    const float* eW2  = (const float*)d_in[5];
    const float* eb2  = (const float*)d_in[6];
    const float* nW1  = (const float*)d_in[7];
    const float* nb1  = (const float*)d_in[8];
    const float* nW2  = (const float*)d_in[9];
    const float* nb2  = (const float*)d_in[10];
    const float* lng  = (const float*)d_in[11];
    const float* lnb  = (const float*)d_in[12];
    float* out = (float*)d_out;

    cudaFuncSetAttribute(precompute_x_kernel,
                         cudaFuncAttributeMaxDynamicSharedMemorySize, PRE_SMEM);
    cudaFuncSetAttribute(edge_kernel,
                         cudaFuncAttributeMaxDynamicSharedMemorySize, EDGE_SMEM);
    cudaFuncSetAttribute(node_kernel,
                         cudaFuncAttributeMaxDynamicSharedMemorySize, NODE_SMEM);

    detect_dtype_kernel<<<1, 32>>>((const int*)eidx);
    convert_idx_kernel<<<(2 * EE + 511) / 512, 512>>>(eidx);
    zero_agg_kernel<<<(NN * HD / 4 + 511) / 512, 512>>>();
    precompute_x_kernel<<<(NN + 63) / 64, 512, PRE_SMEM>>>(h, eW1);
    edge_kernel<<<444, 512, EDGE_SMEM>>>(ea, eW1, eb1, eW2, eb2);
    node_kernel<<<148, 512, NODE_SMEM>>>(h, nW1, nb1, nW2, nb2,
                                         lng, lnb, out);
}